// round 17
// baseline (speedup 1.0000x reference)
#include <cuda_runtime.h>

// ---------------------------------------------------------------------------
// CumulantSOAP, fused single kernel, colstripe layout, ZERO spins, MULTI-WAVE:
//   phase 1 (2368 blocks = 8 colstripes x 296 rowchunks, ~4 waves/SM with
//     CLC work-stealing): each block streams 339 rows x 128 cols (8 warps x
//     different rows, same cols), folds 8 warps in smem, writes 5x128 floats
//     -> g_partial (6 MB, L2-resident; X loaded evict-first via __ldcs).
//   finish (per-colstripe LAST arriver, x8 in parallel, pure continuation):
//     folds 296 chunk-partials for its 128 cols (L2-hot, 8-way + smem),
//     fp32 cumulants, (c - mu) @ W slice -> g_outp[cs][8].
//   final (last of the 8): sums partial outputs -> out, resets counters.
// Deterministic: fixed chunk membership + fixed summation order everywhere.
// Deadlock-free: pure ticket-continuation, no spin loops (multi-wave safe).
// ---------------------------------------------------------------------------

#define NM    5
#define NCS   8            // colstripes of 128 columns
#define NRC   296          // rowchunks (grid = 2368 ~= 4 waves)
#define GTOT  (NCS * NRC)
#define PMAX  1024

__device__ float g_partial[NM * NRC * PMAX];     // [m][rc][col]  (6 MB)
__device__ float g_outp[NCS * 8];                // per-colstripe partial outputs
__device__ float g_cum[NM * PMAX];               // generic-fallback only
__device__ unsigned g_ccs[NCS];                  // per-colstripe arrivals
__device__ unsigned g_cnt3 = 0;                  // finisher tickets
// fallback scratch (separate)
#define GFB   592
__device__ float g_partialF[NM * GFB * PMAX];

// ---- packed f32x2 helpers (Blackwell FFMA2 path, PTX-only) ----------------
static __device__ __forceinline__ unsigned long long f2_mul(unsigned long long a,
                                                            unsigned long long b) {
    unsigned long long d;
    asm("mul.rn.f32x2 %0, %1, %2;" : "=l"(d) : "l"(a), "l"(b));
    return d;
}
static __device__ __forceinline__ unsigned long long f2_add(unsigned long long a,
                                                            unsigned long long b) {
    unsigned long long d;
    asm("add.rn.f32x2 %0, %1, %2;" : "=l"(d) : "l"(a), "l"(b));
    return d;
}
static __device__ __forceinline__ unsigned long long f2_fma(unsigned long long a,
                                                            unsigned long long b,
                                                            unsigned long long c) {
    unsigned long long d;
    asm("fma.rn.f32x2 %0, %1, %2, %3;" : "=l"(d) : "l"(a), "l"(b), "l"(c));
    return d;
}
static __device__ __forceinline__ float2 f2_unpack(unsigned long long v) {
    float2 f;
    asm("mov.b64 {%0, %1}, %2;" : "=f"(f.x), "=f"(f.y) : "l"(v));
    return f;
}

#define ACC(u, s1, s2, s3, s4, s5)                         \
    do {                                                   \
        unsigned long long _x2 = f2_mul((u), (u));         \
        unsigned long long _x3 = f2_mul(_x2, (u));         \
        (s1) = f2_add((s1), (u));                          \
        (s2) = f2_fma((u), (u), (s2));                     \
        (s3) = f2_fma(_x2, (u), (s3));                     \
        (s4) = f2_fma(_x2, _x2, (s4));                     \
        (s5) = f2_fma(_x3, _x2, (s5));                     \
    } while (0)

// ---------------------------------------------------------------------------
__global__ __launch_bounds__(256, 4)
void k_fused(const float* __restrict__ X, const float* __restrict__ mu,
             const float* __restrict__ W, float* __restrict__ out, int N) {
    const int b   = blockIdx.x;
    const int tid = threadIdx.x;
    const int cs  = b & (NCS - 1);        // colstripe 0..7
    const int rc  = b >> 3;               // rowchunk 0..NRC-1
    const int w   = tid >> 5;             // warp 0..7
    const int l   = tid & 31;             // lane

    __shared__ float s_buf[8 * NM * 128]; // 20 KB, reused across phases
    __shared__ float s_cm[NM * 128];      // cumulants - mu
    __shared__ unsigned s_tkt;

    const int chunk = (N + NRC - 1) / NRC;   // 339

    // ================= phase 1: streaming raw moments =================
    {
        const int col4 = cs * 128 + l * 4;
        unsigned long long s1a = 0ULL, s2a = 0ULL, s3a = 0ULL, s4a = 0ULL, s5a = 0ULL;
        unsigned long long s1b = 0ULL, s2b = 0ULL, s3b = 0ULL, s4b = 0ULL, s5b = 0ULL;

        const char* base = (const char*)(X + col4);
        const size_t rowBytes = (size_t)PMAX * sizeof(float);

        const int r1 = min(N, rc * chunk + chunk);
        int r = rc * chunk + w;
        for (; r + 24 < r1; r += 32) {     // 4 rows/thread in flight (step 8)
            ulonglong2 v0 = __ldcs((const ulonglong2*)(base + (size_t)r * rowBytes));
            ulonglong2 v1 = __ldcs((const ulonglong2*)(base + (size_t)(r + 8) * rowBytes));
            ulonglong2 v2 = __ldcs((const ulonglong2*)(base + (size_t)(r + 16) * rowBytes));
            ulonglong2 v3 = __ldcs((const ulonglong2*)(base + (size_t)(r + 24) * rowBytes));
            ACC(v0.x, s1a, s2a, s3a, s4a, s5a);
            ACC(v0.y, s1b, s2b, s3b, s4b, s5b);
            ACC(v1.x, s1a, s2a, s3a, s4a, s5a);
            ACC(v1.y, s1b, s2b, s3b, s4b, s5b);
            ACC(v2.x, s1a, s2a, s3a, s4a, s5a);
            ACC(v2.y, s1b, s2b, s3b, s4b, s5b);
            ACC(v3.x, s1a, s2a, s3a, s4a, s5a);
            ACC(v3.y, s1b, s2b, s3b, s4b, s5b);
        }
        for (; r < r1; r += 8) {
            ulonglong2 v = __ldcs((const ulonglong2*)(base + (size_t)r * rowBytes));
            ACC(v.x, s1a, s2a, s3a, s4a, s5a);
            ACC(v.y, s1b, s2b, s3b, s4b, s5b);
        }

        // write lane moments to smem: s_buf[w][m][l*4..l*4+3]
        float2 a, bb;
        a = f2_unpack(s1a); bb = f2_unpack(s1b);
        *(float4*)&s_buf[w * (NM * 128) + 0 * 128 + l * 4] = make_float4(a.x, a.y, bb.x, bb.y);
        a = f2_unpack(s2a); bb = f2_unpack(s2b);
        *(float4*)&s_buf[w * (NM * 128) + 1 * 128 + l * 4] = make_float4(a.x, a.y, bb.x, bb.y);
        a = f2_unpack(s3a); bb = f2_unpack(s3b);
        *(float4*)&s_buf[w * (NM * 128) + 2 * 128 + l * 4] = make_float4(a.x, a.y, bb.x, bb.y);
        a = f2_unpack(s4a); bb = f2_unpack(s4b);
        *(float4*)&s_buf[w * (NM * 128) + 3 * 128 + l * 4] = make_float4(a.x, a.y, bb.x, bb.y);
        a = f2_unpack(s5a); bb = f2_unpack(s5b);
        *(float4*)&s_buf[w * (NM * 128) + 4 * 128 + l * 4] = make_float4(a.x, a.y, bb.x, bb.y);
    }
    __syncthreads();

    // fold 8 warps -> write 5 x 128 floats (warp m handles moment m)
    if (w < NM) {
        float4 acc = make_float4(0.f, 0.f, 0.f, 0.f);
#pragma unroll
        for (int j = 0; j < 8; j++) {
            const float4 v = *(const float4*)&s_buf[j * (NM * 128) + w * 128 + l * 4];
            acc.x += v.x; acc.y += v.y; acc.z += v.z; acc.w += v.w;
        }
        *(float4*)&g_partial[w * (NRC * PMAX) + rc * PMAX + cs * 128 + l * 4] = acc;
    }

    // ================= arrival (per-colstripe), pure continuation ==========
    __threadfence();
    __syncthreads();
    if (tid == 0) s_tkt = atomicAdd(&g_ccs[cs], 1u);
    __syncthreads();
    if (s_tkt != NRC - 1) return;          // only the LAST chunk of each stripe

    // ================= finish: fold 296 chunks for this stripe =============
    __threadfence();                        // acquire all chunk writes

    {
        const int q = tid & 31;             // col-quad 0..31 (4 cols each)
        const int y = tid >> 5;             // way 0..7
        float4 acc[NM];
#pragma unroll
        for (int m = 0; m < NM; m++) acc[m] = make_float4(0.f, 0.f, 0.f, 0.f);

        for (int j = y; j < NRC; j += 8) {
#pragma unroll
            for (int m = 0; m < NM; m++) {
                const float4 v = *(const float4*)
                    &g_partial[m * (NRC * PMAX) + j * PMAX + cs * 128 + q * 4];
                acc[m].x += v.x; acc[m].y += v.y; acc[m].z += v.z; acc[m].w += v.w;
            }
        }
        __syncthreads();                    // re-use s_buf safely
#pragma unroll
        for (int m = 0; m < NM; m++)
            *(float4*)&s_buf[m * (8 * 128) + y * 128 + q * 4] = acc[m];
    }
    __syncthreads();

    // cumulants for 128 columns (threads 0..127)
    if (tid < 128) {
        const int lc = tid;
        const int col = cs * 128 + lc;
        float t[NM];
#pragma unroll
        for (int m = 0; m < NM; m++) {
            float v = 0.f;
#pragma unroll
            for (int j = 0; j < 8; j++) v += s_buf[m * (8 * 128) + j * 128 + lc];
            t[m] = v;
        }
        const float invN = 1.0f / (float)N;
        const float m1 = t[0] * invN;
        const float r2 = t[1] * invN;
        const float r3 = t[2] * invN;
        const float r4 = t[3] * invN;
        const float r5 = t[4] * invN;
        const float m2 = m1 * m1;
        const float m3 = m2 * m1;

        const float mu2 = r2 - m2;
        const float mu3 = r3 - 3.0f * m1 * r2 + 2.0f * m3;
        const float mu5 = r5 - 5.0f * m1 * r4 + 10.0f * m2 * r3 - 10.0f * m3 * r2
                          + 4.0f * m3 * m2;

        const float* mup = mu + (size_t)col * NM;    // unaligned: scalars
        s_cm[0 * 128 + lc] = m1                        - __ldg(&mup[0]);
        s_cm[1 * 128 + lc] = 0.f                       - __ldg(&mup[1]);
        s_cm[2 * 128 + lc] = mu2                       - __ldg(&mup[2]);
        s_cm[3 * 128 + lc] = (mu3 - 3.0f * mu2 * mu2)  - __ldg(&mup[3]);
        s_cm[4 * 128 + lc] = (mu5 - 10.0f * mu2 * mu3) - __ldg(&mup[4]);
    }
    __syncthreads();

    // projection: warp p -> output k=p over this stripe's 128 cols
    {
        const int p = w;                    // 0..7
        float a = 0.f;
#pragma unroll
        for (int g4 = 0; g4 < 4; g4++) {
            const int lc = l + g4 * 32;
            const int col = cs * 128 + lc;
#pragma unroll
            for (int q = 0; q < NM; q++)
                a += s_cm[q * 128 + lc] * __ldg(&W[(size_t)col * 40 + q * 8 + p]);
        }
#pragma unroll
        for (int o = 16; o > 0; o >>= 1)
            a += __shfl_down_sync(0xffffffffu, a, o);
        if (l == 0) g_outp[cs * 8 + p] = a;
    }

    __threadfence();
    __syncthreads();
    if (tid == 0) s_tkt = atomicAdd(&g_cnt3, 1u);
    __syncthreads();
    if (s_tkt != NCS - 1) return;           // only the LAST finisher remains

    // ================= final: sum 8 partial outputs + reset ================
    __threadfence();
    if (tid < 8) {
        float v = 0.f;
#pragma unroll
        for (int i = 0; i < NCS; i++) v += g_outp[i * 8 + tid];
        out[tid] = v;
    }
    if (tid < NCS) g_ccs[tid] = 0;
    if (tid == 0)  g_cnt3 = 0;
    __threadfence();
}

// ---------------------------------------------------------------------------
// Generic fallback path (K != 8 or P != 1024): 3 separate kernels, fp32.
// ---------------------------------------------------------------------------
__global__ __launch_bounds__(256, 4)
void k_moments(const float* __restrict__ X, int N, int P, int G) {
    const int b = blockIdx.x;
    const int tid = threadIdx.x;
    const int col4 = tid * 4;

    unsigned long long s1a = 0ULL, s2a = 0ULL, s3a = 0ULL, s4a = 0ULL, s5a = 0ULL;
    unsigned long long s1b = 0ULL, s2b = 0ULL, s3b = 0ULL, s4b = 0ULL, s5b = 0ULL;

    const char* base = (const char*)(X + col4);
    const size_t rowBytes = (size_t)P * sizeof(float);

    for (int r = b; r < N; r += G) {
        ulonglong2 v = __ldcs((const ulonglong2*)(base + (size_t)r * rowBytes));
        ACC(v.x, s1a, s2a, s3a, s4a, s5a);
        ACC(v.y, s1b, s2b, s3b, s4b, s5b);
    }

    const size_t GP = (size_t)G * P;
    float* o = g_partialF + (size_t)b * P + col4;
    float2 a, bb;
    a = f2_unpack(s1a); bb = f2_unpack(s1b);
    *(float4*)(o + 0 * GP) = make_float4(a.x, a.y, bb.x, bb.y);
    a = f2_unpack(s2a); bb = f2_unpack(s2b);
    *(float4*)(o + 1 * GP) = make_float4(a.x, a.y, bb.x, bb.y);
    a = f2_unpack(s3a); bb = f2_unpack(s3b);
    *(float4*)(o + 2 * GP) = make_float4(a.x, a.y, bb.x, bb.y);
    a = f2_unpack(s4a); bb = f2_unpack(s4b);
    *(float4*)(o + 3 * GP) = make_float4(a.x, a.y, bb.x, bb.y);
    a = f2_unpack(s5a); bb = f2_unpack(s5b);
    *(float4*)(o + 4 * GP) = make_float4(a.x, a.y, bb.x, bb.y);
}

__global__ __launch_bounds__(128)
void k_reduceB_gen(const float* __restrict__ mu, int N, int P, int G) {
    const int col = blockIdx.x * 128 + threadIdx.x;
    if (col >= P) return;
    const size_t GP = (size_t)G * P;

    float t[NM] = {0.f, 0.f, 0.f, 0.f, 0.f};
    for (int bb = 0; bb < G; bb++) {
#pragma unroll
        for (int m = 0; m < NM; m++)
            t[m] += g_partialF[(size_t)m * GP + (size_t)bb * P + col];
    }

    const float invN = 1.0f / (float)N;
    const float m1 = t[0] * invN;
    const float r2 = t[1] * invN;
    const float r3 = t[2] * invN;
    const float r4 = t[3] * invN;
    const float r5 = t[4] * invN;
    const float m2 = m1 * m1;
    const float m3 = m2 * m1;

    const float mu2 = r2 - m2;
    const float mu3 = r3 - 3.0f * m1 * r2 + 2.0f * m3;
    const float mu5 = r5 - 5.0f * m1 * r4 + 10.0f * m2 * r3 - 10.0f * m3 * r2
                      + 4.0f * m3 * m2;

    const int j = col * NM;
    g_cum[j + 0] = m1 - mu[j + 0];
    g_cum[j + 1] = 0.f - mu[j + 1];
    g_cum[j + 2] = mu2 - mu[j + 2];
    g_cum[j + 3] = (mu3 - 3.0f * mu2 * mu2) - mu[j + 3];
    g_cum[j + 4] = (mu5 - 10.0f * mu2 * mu3) - mu[j + 4];
}

__global__ void k_project_gen(const float* __restrict__ W, float* __restrict__ out,
                              int P5, int K) {
    const int w = blockIdx.x;
    const int lane = threadIdx.x;
    float acc = 0.f;
    for (int i = lane; i < P5; i += 32)
        acc += g_cum[i] * W[(size_t)i * K + w];
#pragma unroll
    for (int o = 16; o > 0; o >>= 1)
        acc += __shfl_down_sync(0xffffffffu, acc, o);
    if (lane == 0) out[w] = acc;
}

// ---------------------------------------------------------------------------
extern "C" void kernel_launch(void* const* d_in, const int* in_sizes, int n_in,
                              void* d_out, int out_size) {
    const float* X  = (const float*)d_in[0];
    const float* mu = (const float*)d_in[1];
    const float* W  = (const float*)d_in[2];
    float* out = (float*)d_out;

    const int P5 = in_sizes[1];          // P * 5
    const int P  = P5 / NM;              // 1024
    const int N  = in_sizes[0] / P;      // 100000
    const int K  = in_sizes[2] / P5;     // 8

    if (K == 8 && P == 1024) {
        k_fused<<<GTOT, 256>>>(X, mu, W, out, N);
    } else {
        const int Gg = GFB;
        k_moments<<<Gg, P / 4>>>(X, N, P, Gg);
        k_reduceB_gen<<<(P + 127) / 128, 128>>>(mu, N, P, Gg);
        k_project_gen<<<K, 32>>>(W, out, P5, K);
    }
}